// round 11
// baseline (speedup 1.0000x reference)
#include <cuda_runtime.h>
#include <cstdint>

// DigitCaps, round 11: round-10 kernel with the seg accumulator as
// COLUMN-MAJOR ulonglong2 accq2[20][128] (word = c*2 + dquad).
//  - scatter: 2 LDS.128 + 4 add2 + 2 STS.128 per vote (same count as r10)
//  - lane stride 16B contiguous -> conflict-free
//  - acc = 40960B -> pool = 45504B = round-8's pool -> 5 blocks/SM (proven)
//  - tail: per-warp batched shuffle reduce (5 independent words/warp)
// B=128, J=4608, INPUT_D=8, D=8, M=4, C=10, N=J*M=18432.

#define J_TOTAL 4608
#define JT 4
#define TPB 128
#define NB (J_TOTAL / JT)      // 1152 caps blocks
#define WSTR 264               // padded floats per j-row of W in smem
#define SJT 16                 // j's per S-block
#define SNB (J_TOTAL / SJT)    // 288 S blocks
#define NBLK (NB + SNB)        // 1440 total
#define NW2 20                 // ulonglong2 words per slice: c*2 + dquad

// pool (floats): accq2[0,10240) (= ulonglong2[20][128]) | Wsh[10240,11296) |
// dcsh[11296,11376). wsd (S path) aliases accq2. dcn (tail) aliases Wsh.
#define POOL_FLOATS 11376      // 45504 B -> 5 blocks/SM (measured, round 8)
#define OFF_WSH  10240
#define OFF_DCSH 11296

__device__ float g_S[1024];     // S[b*8+d]
__device__ float g_seg[80];     // winner-gated sums [c*8+d]
__device__ float g_cnt[16];     // winner counts [c]
__device__ unsigned g_ticket;

typedef unsigned long long u64;

static __device__ __forceinline__ u64 pack2(float lo, float hi) {
    u64 r;
    asm("mov.b64 %0, {%1, %2};"
        : "=l"(r) : "r"(__float_as_uint(lo)), "r"(__float_as_uint(hi)));
    return r;
}
static __device__ __forceinline__ void unpack2(u64 v, float& lo, float& hi) {
    unsigned a, b;
    asm("mov.b64 {%0, %1}, %2;" : "=r"(a), "=r"(b) : "l"(v));
    lo = __uint_as_float(a); hi = __uint_as_float(b);
}
static __device__ __forceinline__ u64 fma2(u64 a, u64 b, u64 c) {
    u64 d;
    asm("fma.rn.f32x2 %0, %1, %2, %3;" : "=l"(d) : "l"(a), "l"(b), "l"(c));
    return d;
}
static __device__ __forceinline__ u64 mul2(u64 a, u64 b) {
    u64 d;
    asm("mul.rn.f32x2 %0, %1, %2;" : "=l"(d) : "l"(a), "l"(b));
    return d;
}
static __device__ __forceinline__ u64 add2(u64 a, u64 b) {
    u64 d;
    asm("add.rn.f32x2 %0, %1, %2;" : "=l"(d) : "l"(a), "l"(b));
    return d;
}
static __device__ __forceinline__ u64 shfl_xor64(u64 v, int m) {
    return (u64)__shfl_xor_sync(0xFFFFFFFFu, v, m);
}

__global__ __launch_bounds__(TPB, 5) void caps_kernel(
    const float* __restrict__ x,    // [B, J, 8]
    const float* __restrict__ Wg,   // [J, 8, 32]
    const float* __restrict__ dc,   // [10, 8]
    float* __restrict__ out, int out_size)
{
    __shared__ __align__(16) float pool[POOL_FLOATS];
    __shared__ unsigned s_last;

    ulonglong2* accq2 = reinterpret_cast<ulonglong2*>(pool);  // [NW2][TPB]
    float* Wsh  = pool + OFF_WSH;
    float* dcsh = pool + OFF_DCSH;
    float* dcn  = pool + OFF_WSH;   // tail-only; Wsh dead by then
    float* wsd  = pool;             // S path aliases accq2

    const int t = threadIdx.x;

    if (blockIdx.x >= NB) {
        // ===== S path: S[b,d] += sum_{j in tile, i} x[b,j,i]*WS[j,i,d] =====
        const int jbase = (blockIdx.x - NB) * SJT;
        for (int e = t; e < SJT * 64; e += TPB) {
            int jj = e >> 6, k = e & 63, i = k >> 3, d = k & 7;
            const float* wp = Wg + (size_t)(jbase + jj) * 256 + i * 32 + d;
            wsd[e] = (wp[0] + wp[8]) + (wp[16] + wp[24]);
        }
        __syncthreads();

        u64 accA[4], accB[4];
        #pragma unroll
        for (int p = 0; p < 4; p++) { accA[p] = 0ull; accB[p] = 0ull; }

        const float* xrow = x + ((size_t)t * J_TOTAL + jbase) * 8;
        #pragma unroll
        for (int jj = 0; jj < SJT; jj += 2) {
            const float4* xpA = reinterpret_cast<const float4*>(xrow + jj * 8);
            const float4* xpB = reinterpret_cast<const float4*>(xrow + jj * 8 + 8);
            float4 a0 = xpA[0], a1 = xpA[1], b0 = xpB[0], b1 = xpB[1];
            float xa[8] = {a0.x, a0.y, a0.z, a0.w, a1.x, a1.y, a1.z, a1.w};
            float xb[8] = {b0.x, b0.y, b0.z, b0.w, b1.x, b1.y, b1.z, b1.w};
            #pragma unroll
            for (int i = 0; i < 8; i++) {
                u64 xxA = pack2(xa[i], xa[i]);
                u64 xxB = pack2(xb[i], xb[i]);
                const ulonglong2* wA = reinterpret_cast<const ulonglong2*>(
                    &wsd[jj * 64 + i * 8]);
                const ulonglong2* wB = reinterpret_cast<const ulonglong2*>(
                    &wsd[(jj + 1) * 64 + i * 8]);
                ulonglong2 wa0 = wA[0], wa1 = wA[1];
                ulonglong2 wb0 = wB[0], wb1 = wB[1];
                accA[0] = fma2(xxA, wa0.x, accA[0]);
                accA[1] = fma2(xxA, wa0.y, accA[1]);
                accA[2] = fma2(xxA, wa1.x, accA[2]);
                accA[3] = fma2(xxA, wa1.y, accA[3]);
                accB[0] = fma2(xxB, wb0.x, accB[0]);
                accB[1] = fma2(xxB, wb0.y, accB[1]);
                accB[2] = fma2(xxB, wb1.x, accB[2]);
                accB[3] = fma2(xxB, wb1.y, accB[3]);
            }
        }
        #pragma unroll
        for (int p = 0; p < 4; p++) {
            u64 v = add2(accA[p], accB[p]);
            float lo, hi; unpack2(v, lo, hi);
            atomicAdd(&g_S[t * 8 + p * 2],     lo);
            atomicAdd(&g_S[t * 8 + p * 2 + 1], hi);
        }
    } else {
        // ===== caps path =====
        const int tj = t & 3;
        const int bg = t >> 2;
        const int j  = blockIdx.x * JT + tj;

        {
            const float4* src = reinterpret_cast<const float4*>(Wg)
                              + (size_t)blockIdx.x * (JT * 64);
            #pragma unroll
            for (int r = 0; r < 2; r++) {
                int g = t + r * TPB, jj = g >> 6, rem = g & 63;
                *reinterpret_cast<float4*>(&Wsh[jj * WSTR + rem * 4]) = src[g];
            }
        }
        if (t < 80) dcsh[t] = dc[t];
        // zero my column (lane stride 16B -> conflict-free)
        {
            ulonglong2 z; z.x = 0ull; z.y = 0ull;
            #pragma unroll
            for (int w = 0; w < NW2; w++) accq2[w * TPB + t] = z;
        }
        __syncthreads();

        // x for my 4 b's (scalar, 32 regs)
        float xv[4][8];
        #pragma unroll
        for (int bb = 0; bb < 4; bb++) {
            const float4* xp = reinterpret_cast<const float4*>(
                x + ((size_t)(bg * 4 + bb) * J_TOTAL + j) * 8);
            float4 a = xp[0], b = xp[1];
            xv[bb][0]=a.x; xv[bb][1]=a.y; xv[bb][2]=a.z; xv[bb][3]=a.w;
            xv[bb][4]=b.x; xv[bb][5]=b.y; xv[bb][6]=b.z; xv[bb][7]=b.w;
        }

        u64 cnt64 = 0ull;

        #pragma unroll
        for (int m = 0; m < 4; m++) {
            // u2[bb][p] = packed pair {u[2p], u[2p+1]} over d
            u64 u2[4][4];
            #pragma unroll
            for (int bb = 0; bb < 4; bb++)
                #pragma unroll
                for (int p = 0; p < 4; p++) u2[bb][p] = 0ull;
            #pragma unroll
            for (int i = 0; i < 8; i++) {
                const ulonglong2* wp = reinterpret_cast<const ulonglong2*>(
                    &Wsh[tj * WSTR + i * 32 + m * 8]);
                ulonglong2 wA = wp[0], wB = wp[1];
                #pragma unroll
                for (int bb = 0; bb < 4; bb++) {
                    u64 xx = pack2(xv[bb][i], xv[bb][i]);
                    u2[bb][0] = fma2(xx, wA.x, u2[bb][0]);
                    u2[bb][1] = fma2(xx, wA.y, u2[bb][1]);
                    u2[bb][2] = fma2(xx, wB.x, u2[bb][2]);
                    u2[bb][3] = fma2(xx, wB.y, u2[bb][3]);
                }
            }

            // argmax_c <u, dc[c]> (strict >, first max)
            float best[4]; int bc[4];
            #pragma unroll
            for (int bb = 0; bb < 4; bb++) { best[bb] = -3.402823466e38f; bc[bb] = 0; }
            #pragma unroll
            for (int c = 0; c < 10; c++) {
                const ulonglong2* dpp =
                    reinterpret_cast<const ulonglong2*>(&dcsh[c * 8]);
                ulonglong2 dA = dpp[0], dB = dpp[1];
                #pragma unroll
                for (int bb = 0; bb < 4; bb++) {
                    u64 s2 = mul2(u2[bb][0], dA.x);
                    s2 = fma2(u2[bb][1], dA.y, s2);
                    s2 = fma2(u2[bb][2], dB.x, s2);
                    s2 = fma2(u2[bb][3], dB.y, s2);
                    float lo, hi; unpack2(s2, lo, hi);
                    float s = lo + hi;
                    if (s > best[bb]) { best[bb] = s; bc[bb] = c; }
                }
            }

            // winner-gated accumulation: conflict-free column .128 RMW
            #pragma unroll
            for (int bb = 0; bb < 4; bb++) {
                cnt64 += 1ull << (bc[bb] * 6);
                ulonglong2* base = accq2 + bc[bb] * 2 * TPB + t;
                ulonglong2 a0 = base[0], a1 = base[TPB];
                a0.x = add2(a0.x, u2[bb][0]); a0.y = add2(a0.y, u2[bb][1]);
                a1.x = add2(a1.x, u2[bb][2]); a1.y = add2(a1.y, u2[bb][3]);
                base[0]   = a0;
                base[TPB] = a1;
            }
        }

        // counts: warp REDUX per class
        {
            int lane = t & 31;
            #pragma unroll
            for (int c = 0; c < 10; c++) {
                unsigned v = (unsigned)((cnt64 >> (6 * c)) & 63ull);
                unsigned s = __reduce_add_sync(0xFFFFFFFFu, v);
                if (lane == 0) atomicAdd(&g_cnt[c], (float)s);
            }
        }

        __syncthreads();
        // reduce 20 ull2-words x 128 columns: each warp owns 5 words (ILP)
        {
            const int wrp  = t >> 5;
            const int lane = t & 31;
            #pragma unroll
            for (int k = 0; k < 5; k++) {
                int w = wrp * 5 + k;                 // 0..19
                const ulonglong2* row = accq2 + w * TPB;
                ulonglong2 v0 = row[lane],      v1 = row[lane + 32];
                ulonglong2 v2 = row[lane + 64], v3 = row[lane + 96];
                u64 sx = add2(add2(v0.x, v1.x), add2(v2.x, v3.x));
                u64 sy = add2(add2(v0.y, v1.y), add2(v2.y, v3.y));
                #pragma unroll
                for (int msk = 1; msk < 32; msk <<= 1) {
                    sx = add2(sx, shfl_xor64(sx, msk));
                    sy = add2(sy, shfl_xor64(sy, msk));
                }
                if (lane == 0) {
                    int c = w >> 1, h = w & 1;
                    float lo, hi;
                    unpack2(sx, lo, hi);
                    atomicAdd(&g_seg[c * 8 + h * 4 + 0], lo);
                    atomicAdd(&g_seg[c * 8 + h * 4 + 1], hi);
                    unpack2(sy, lo, hi);
                    atomicAdd(&g_seg[c * 8 + h * 4 + 2], lo);
                    atomicAdd(&g_seg[c * 8 + h * 4 + 3], hi);
                }
            }
        }
    }

    // ===== common tail: last-block finish + reset =====
    __threadfence();
    __syncthreads();
    if (t == 0) s_last = (atomicAdd(&g_ticket, 1u) == (unsigned)(NBLK - 1)) ? 1u : 0u;
    __syncthreads();
    if (!s_last) return;

    if (t < 80) {
        int c = t >> 3;
        float d0  = dc[t];
        float seg = __ldcg(&g_seg[t]);
        float cnt = __ldcg(&g_cnt[c]);
        float v = d0 + (seg - cnt * d0) * (1.0f / 2359296.0f);  // /(B*N)
        dcn[t] = v;
        if (out_size >= 1360) out[1280 + t] = v;
        if (out_size == 80)   out[t] = v;
    }
    __syncthreads();
    if (out_size >= 1280) {
        float sv[8];
        #pragma unroll
        for (int d = 0; d < 8; d++) sv[d] = __ldcg(&g_S[t * 8 + d]);
        #pragma unroll
        for (int c = 0; c < 10; c++) {
            float s = 0.f;
            #pragma unroll
            for (int d = 0; d < 8; d++) s = fmaf(sv[d], dcn[c * 8 + d], s);
            out[t * 10 + c] = s * (1.0f / 18432.0f);
        }
    }
    // reset for next graph replay
    #pragma unroll
    for (int d = 0; d < 8; d++) g_S[t * 8 + d] = 0.f;
    if (t < 80) g_seg[t] = 0.f;
    if (t < 16) g_cnt[t] = 0.f;
    if (t == 0) g_ticket = 0u;
}

extern "C" void kernel_launch(void* const* d_in, const int* in_sizes, int n_in,
                              void* d_out, int out_size)
{
    // x = 128*4608*8 = 4718592, W = 4608*8*32 = 1179648, dc = 80.
    const float* x  = nullptr;
    const float* W  = nullptr;
    const float* dc = nullptr;
    for (int i = 0; i < n_in; i++) {
        if (in_sizes[i] == 4718592)      x  = (const float*)d_in[i];
        else if (in_sizes[i] == 1179648) W  = (const float*)d_in[i];
        else if (in_sizes[i] == 80)      dc = (const float*)d_in[i];
    }
    if (!x)  x  = (const float*)d_in[0];
    if (!W)  W  = (const float*)d_in[1];
    if (!dc) dc = (const float*)d_in[2];

    caps_kernel<<<NBLK, TPB>>>(x, W, dc, (float*)d_out, out_size);
}

// round 12
// speedup vs baseline: 1.3742x; 1.3742x over previous
#include <cuda_runtime.h>
#include <cstdint>

// DigitCaps, round 12: round-10 base (best, 88.1us) with ONE change — the
// argmax select chain (FSETP@13cyc x10 serial) replaced by a branchless
// monotonic-integer-key max (IMNMX@4cyc, alu pipe). key = mono(s)&~15 | (15-c)
// preserves the first-max tie rule; 4 masked mantissa bits are far below the
// 1e-3 tolerance.
// B=128, J=4608, INPUT_D=8, D=8, M=4, C=10, N=J*M=18432.

#define J_TOTAL 4608
#define JT 4
#define TPB 128
#define NB (J_TOTAL / JT)      // 1152 caps blocks
#define WSTR 264               // padded floats per j-row of W in smem
#define ASTR 84                // per-thread seg-slice stride
#define SJT 16                 // j's per S-block
#define SNB (J_TOTAL / SJT)    // 288 S blocks
#define NBLK (NB + SNB)        // 1440 total

// pool (floats): acc[0,10752) | Wsh[10752,11808) | dcsh[11808,11888) |
// dcn[11888,11968).  wsd (S path) aliases acc[0,1024).
#define POOL_FLOATS 11968      // 47872 B -> 4 blocks/SM
#define OFF_WSH  10752
#define OFF_DCSH 11808
#define OFF_DCN  11888

__device__ float g_S[1024];     // S[b*8+d] = sum_n u[b,n,d]
__device__ float g_seg[80];     // winner-gated sums [c*8+d]
__device__ float g_cnt[16];     // winner counts [c]
__device__ unsigned g_ticket;

typedef unsigned long long u64;

static __device__ __forceinline__ u64 pack2(float lo, float hi) {
    u64 r;
    asm("mov.b64 %0, {%1, %2};"
        : "=l"(r) : "r"(__float_as_uint(lo)), "r"(__float_as_uint(hi)));
    return r;
}
static __device__ __forceinline__ void unpack2(u64 v, float& lo, float& hi) {
    unsigned a, b;
    asm("mov.b64 {%0, %1}, %2;" : "=r"(a), "=r"(b) : "l"(v));
    lo = __uint_as_float(a); hi = __uint_as_float(b);
}
static __device__ __forceinline__ u64 fma2(u64 a, u64 b, u64 c) {
    u64 d;
    asm("fma.rn.f32x2 %0, %1, %2, %3;" : "=l"(d) : "l"(a), "l"(b), "l"(c));
    return d;
}
static __device__ __forceinline__ u64 mul2(u64 a, u64 b) {
    u64 d;
    asm("mul.rn.f32x2 %0, %1, %2;" : "=l"(d) : "l"(a), "l"(b));
    return d;
}
static __device__ __forceinline__ u64 add2(u64 a, u64 b) {
    u64 d;
    asm("add.rn.f32x2 %0, %1, %2;" : "=l"(d) : "l"(a), "l"(b));
    return d;
}
// order-preserving float -> uint map (positive: +0x80000000; negative: ~bits)
static __device__ __forceinline__ unsigned fmono(float s) {
    unsigned u = __float_as_uint(s);
    return u ^ (unsigned)(((int)u >> 31) | 0x80000000);
}

__global__ __launch_bounds__(TPB, 4) void caps_kernel(
    const float* __restrict__ x,    // [B, J, 8]
    const float* __restrict__ Wg,   // [J, 8, 32]
    const float* __restrict__ dc,   // [10, 8]
    float* __restrict__ out, int out_size)
{
    __shared__ __align__(16) float pool[POOL_FLOATS];
    __shared__ unsigned s_last;

    float* acc  = pool;
    float* Wsh  = pool + OFF_WSH;
    float* dcsh = pool + OFF_DCSH;
    float* dcn  = pool + OFF_DCN;
    float* wsd  = pool;             // S path aliases acc

    const int t = threadIdx.x;

    if (blockIdx.x >= NB) {
        // ===== S path: S[b,d] += sum_{j in tile, i} x[b,j,i]*WS[j,i,d] =====
        const int jbase = (blockIdx.x - NB) * SJT;
        for (int e = t; e < SJT * 64; e += TPB) {
            int jj = e >> 6, k = e & 63, i = k >> 3, d = k & 7;
            const float* wp = Wg + (size_t)(jbase + jj) * 256 + i * 32 + d;
            wsd[e] = (wp[0] + wp[8]) + (wp[16] + wp[24]);
        }
        __syncthreads();

        u64 accA[4], accB[4];
        #pragma unroll
        for (int p = 0; p < 4; p++) { accA[p] = 0ull; accB[p] = 0ull; }

        const float* xrow = x + ((size_t)t * J_TOTAL + jbase) * 8;
        #pragma unroll
        for (int jj = 0; jj < SJT; jj += 2) {
            const float4* xpA = reinterpret_cast<const float4*>(xrow + jj * 8);
            const float4* xpB = reinterpret_cast<const float4*>(xrow + jj * 8 + 8);
            float4 a0 = xpA[0], a1 = xpA[1], b0 = xpB[0], b1 = xpB[1];
            float xa[8] = {a0.x, a0.y, a0.z, a0.w, a1.x, a1.y, a1.z, a1.w};
            float xb[8] = {b0.x, b0.y, b0.z, b0.w, b1.x, b1.y, b1.z, b1.w};
            #pragma unroll
            for (int i = 0; i < 8; i++) {
                u64 xxA = pack2(xa[i], xa[i]);
                u64 xxB = pack2(xb[i], xb[i]);
                const ulonglong2* wA = reinterpret_cast<const ulonglong2*>(
                    &wsd[jj * 64 + i * 8]);
                const ulonglong2* wB = reinterpret_cast<const ulonglong2*>(
                    &wsd[(jj + 1) * 64 + i * 8]);
                ulonglong2 wa0 = wA[0], wa1 = wA[1];
                ulonglong2 wb0 = wB[0], wb1 = wB[1];
                accA[0] = fma2(xxA, wa0.x, accA[0]);
                accA[1] = fma2(xxA, wa0.y, accA[1]);
                accA[2] = fma2(xxA, wa1.x, accA[2]);
                accA[3] = fma2(xxA, wa1.y, accA[3]);
                accB[0] = fma2(xxB, wb0.x, accB[0]);
                accB[1] = fma2(xxB, wb0.y, accB[1]);
                accB[2] = fma2(xxB, wb1.x, accB[2]);
                accB[3] = fma2(xxB, wb1.y, accB[3]);
            }
        }
        #pragma unroll
        for (int p = 0; p < 4; p++) {
            u64 v = add2(accA[p], accB[p]);
            float lo, hi; unpack2(v, lo, hi);
            atomicAdd(&g_S[t * 8 + p * 2],     lo);
            atomicAdd(&g_S[t * 8 + p * 2 + 1], hi);
        }
    } else {
        // ===== caps path (round-10 structure) =====
        const int tj = t & 3;
        const int bg = t >> 2;
        const int j  = blockIdx.x * JT + tj;

        {
            const float4* src = reinterpret_cast<const float4*>(Wg)
                              + (size_t)blockIdx.x * (JT * 64);
            #pragma unroll
            for (int r = 0; r < 2; r++) {
                int g = t + r * TPB, jj = g >> 6, rem = g & 63;
                *reinterpret_cast<float4*>(&Wsh[jj * WSTR + rem * 4]) = src[g];
            }
        }
        if (t < 80) dcsh[t] = dc[t];
        float* myacc = &acc[t * ASTR];
        #pragma unroll
        for (int q = 0; q < 21; q++)
            reinterpret_cast<float4*>(myacc)[q] = make_float4(0.f, 0.f, 0.f, 0.f);
        __syncthreads();

        // x for my 4 b's (scalar, 32 regs)
        float xv[4][8];
        #pragma unroll
        for (int bb = 0; bb < 4; bb++) {
            const float4* xp = reinterpret_cast<const float4*>(
                x + ((size_t)(bg * 4 + bb) * J_TOTAL + j) * 8);
            float4 a = xp[0], b = xp[1];
            xv[bb][0]=a.x; xv[bb][1]=a.y; xv[bb][2]=a.z; xv[bb][3]=a.w;
            xv[bb][4]=b.x; xv[bb][5]=b.y; xv[bb][6]=b.z; xv[bb][7]=b.w;
        }

        u64 cnt64 = 0ull;

        #pragma unroll
        for (int m = 0; m < 4; m++) {
            // u2[bb][p] = packed pair {u[2p], u[2p+1]} over d
            u64 u2[4][4];
            #pragma unroll
            for (int bb = 0; bb < 4; bb++)
                #pragma unroll
                for (int p = 0; p < 4; p++) u2[bb][p] = 0ull;
            #pragma unroll
            for (int i = 0; i < 8; i++) {
                const ulonglong2* wp = reinterpret_cast<const ulonglong2*>(
                    &Wsh[tj * WSTR + i * 32 + m * 8]);
                ulonglong2 wA = wp[0], wB = wp[1];
                #pragma unroll
                for (int bb = 0; bb < 4; bb++) {
                    u64 xx = pack2(xv[bb][i], xv[bb][i]);
                    u2[bb][0] = fma2(xx, wA.x, u2[bb][0]);
                    u2[bb][1] = fma2(xx, wA.y, u2[bb][1]);
                    u2[bb][2] = fma2(xx, wB.x, u2[bb][2]);
                    u2[bb][3] = fma2(xx, wB.y, u2[bb][3]);
                }
            }

            // argmax_c <u, dc[c]> via monotonic-integer-key max (IMNMX chain):
            // key = (mono(s) & ~15) | (15-c); first-max/smallest-c tie rule kept.
            unsigned best[4];
            #pragma unroll
            for (int bb = 0; bb < 4; bb++) best[bb] = 0u;
            #pragma unroll
            for (int c = 0; c < 10; c++) {
                const ulonglong2* dpp =
                    reinterpret_cast<const ulonglong2*>(&dcsh[c * 8]);
                ulonglong2 dA = dpp[0], dB = dpp[1];
                #pragma unroll
                for (int bb = 0; bb < 4; bb++) {
                    u64 s2 = mul2(u2[bb][0], dA.x);
                    s2 = fma2(u2[bb][1], dA.y, s2);
                    s2 = fma2(u2[bb][2], dB.x, s2);
                    s2 = fma2(u2[bb][3], dB.y, s2);
                    float lo, hi; unpack2(s2, lo, hi);
                    unsigned key = (fmono(lo + hi) & 0xFFFFFFF0u)
                                 | (unsigned)(15 - c);
                    best[bb] = best[bb] > key ? best[bb] : key;  // IMNMX.U32
                }
            }
            int bc[4];
            #pragma unroll
            for (int bb = 0; bb < 4; bb++) bc[bb] = 15 - (int)(best[bb] & 15u);

            // winner-gated accumulation into private slice (packed adds)
            #pragma unroll
            for (int bb = 0; bb < 4; bb++) {
                cnt64 += 1ull << (bc[bb] * 6);
                ulonglong2* p2 = reinterpret_cast<ulonglong2*>(myacc + bc[bb] * 8);
                ulonglong2 a0 = p2[0], a1 = p2[1];
                a0.x = add2(a0.x, u2[bb][0]); a0.y = add2(a0.y, u2[bb][1]);
                a1.x = add2(a1.x, u2[bb][2]); a1.y = add2(a1.y, u2[bb][3]);
                p2[0] = a0; p2[1] = a1;
            }
        }

        // counts: warp REDUX per class
        {
            int lane = t & 31;
            #pragma unroll
            for (int c = 0; c < 10; c++) {
                unsigned v = (unsigned)((cnt64 >> (6 * c)) & 63ull);
                unsigned s = __reduce_add_sync(0xFFFFFFFFu, v);
                if (lane == 0) atomicAdd(&g_cnt[c], (float)s);
            }
        }

        __syncthreads();
        // block-reduce the 128 seg slices (column sweep)
        if (t < 80) {
            float s0 = 0.f, s1 = 0.f, s2 = 0.f, s3 = 0.f;
            #pragma unroll 4
            for (int r = 0; r < TPB; r += 4) {
                s0 += acc[(r + 0) * ASTR + t];
                s1 += acc[(r + 1) * ASTR + t];
                s2 += acc[(r + 2) * ASTR + t];
                s3 += acc[(r + 3) * ASTR + t];
            }
            atomicAdd(&g_seg[t], (s0 + s1) + (s2 + s3));
        }
    }

    // ===== common tail: last-block finish + reset =====
    __threadfence();
    __syncthreads();
    if (t == 0) s_last = (atomicAdd(&g_ticket, 1u) == (unsigned)(NBLK - 1)) ? 1u : 0u;
    __syncthreads();
    if (!s_last) return;

    if (t < 80) {
        int c = t >> 3;
        float d0  = dc[t];
        float seg = __ldcg(&g_seg[t]);
        float cnt = __ldcg(&g_cnt[c]);
        float v = d0 + (seg - cnt * d0) * (1.0f / 2359296.0f);  // /(B*N)
        dcn[t] = v;
        if (out_size >= 1360) out[1280 + t] = v;
        if (out_size == 80)   out[t] = v;
    }
    __syncthreads();
    if (out_size >= 1280) {
        float sv[8];
        #pragma unroll
        for (int d = 0; d < 8; d++) sv[d] = __ldcg(&g_S[t * 8 + d]);
        #pragma unroll
        for (int c = 0; c < 10; c++) {
            float s = 0.f;
            #pragma unroll
            for (int d = 0; d < 8; d++) s = fmaf(sv[d], dcn[c * 8 + d], s);
            out[t * 10 + c] = s * (1.0f / 18432.0f);
        }
    }
    // reset for next graph replay
    #pragma unroll
    for (int d = 0; d < 8; d++) g_S[t * 8 + d] = 0.f;
    if (t < 80) g_seg[t] = 0.f;
    if (t < 16) g_cnt[t] = 0.f;
    if (t == 0) g_ticket = 0u;
}

extern "C" void kernel_launch(void* const* d_in, const int* in_sizes, int n_in,
                              void* d_out, int out_size)
{
    // x = 128*4608*8 = 4718592, W = 4608*8*32 = 1179648, dc = 80.
    const float* x  = nullptr;
    const float* W  = nullptr;
    const float* dc = nullptr;
    for (int i = 0; i < n_in; i++) {
        if (in_sizes[i] == 4718592)      x  = (const float*)d_in[i];
        else if (in_sizes[i] == 1179648) W  = (const float*)d_in[i];
        else if (in_sizes[i] == 80)      dc = (const float*)d_in[i];
    }
    if (!x)  x  = (const float*)d_in[0];
    if (!W)  W  = (const float*)d_in[1];
    if (!dc) dc = (const float*)d_in[2];

    caps_kernel<<<NBLK, TPB>>>(x, W, dc, (float*)d_out, out_size);
}